// round 2
// baseline (speedup 1.0000x reference)
#include <cuda_runtime.h>
#include <cstdint>

#define D_MODEL 1024
#define HEADS   16
#define DK      64
#define BATCH   2
#define SEQ     2048
#define MTOK    (BATCH * SEQ)   // 4096

// Scratch (allocation-free: static device globals)
__device__ float g_q[(size_t)MTOK * D_MODEL];
__device__ float g_k[(size_t)MTOK * D_MODEL];
__device__ float g_v[(size_t)MTOK * D_MODEL];
__device__ float g_ctx[(size_t)MTOK * D_MODEL];

// ---------------------------------------------------------------------------
// C[m][n] = sum_k A[m][k] * B[n][k]   (A: MxK row-major, B: NxK row-major)
// 128x128 block tile, BK=8, 256 threads, 8x8 per-thread micro-tile.
// ---------------------------------------------------------------------------
__device__ __forceinline__ void sgemm_nt_body(const float* __restrict__ A,
                                              const float* __restrict__ B,
                                              float* __restrict__ C,
                                              int K, int N) {
    __shared__ __align__(16) float As[8][128];
    __shared__ __align__(16) float Bs[8][128];

    const int tid  = threadIdx.x;
    const int bm   = blockIdx.y * 128;
    const int bn   = blockIdx.x * 128;
    const int lrow = tid >> 1;          // 0..127
    const int lcol = (tid & 1) * 4;     // 0 or 4
    const int tx   = tid & 15;
    const int ty   = tid >> 4;

    const float* Ap = A + (size_t)(bm + lrow) * K + lcol;
    const float* Bp = B + (size_t)(bn + lrow) * K + lcol;

    float acc[8][8];
#pragma unroll
    for (int i = 0; i < 8; i++)
#pragma unroll
        for (int j = 0; j < 8; j++) acc[i][j] = 0.f;

    for (int k0 = 0; k0 < K; k0 += 8) {
        float4 av = *(const float4*)(Ap + k0);
        float4 bv = *(const float4*)(Bp + k0);
        __syncthreads();
        As[lcol + 0][lrow] = av.x;
        As[lcol + 1][lrow] = av.y;
        As[lcol + 2][lrow] = av.z;
        As[lcol + 3][lrow] = av.w;
        Bs[lcol + 0][lrow] = bv.x;
        Bs[lcol + 1][lrow] = bv.y;
        Bs[lcol + 2][lrow] = bv.z;
        Bs[lcol + 3][lrow] = bv.w;
        __syncthreads();
#pragma unroll
        for (int kk = 0; kk < 8; kk++) {
            float4 a0 = *(const float4*)&As[kk][ty * 8];
            float4 a1 = *(const float4*)&As[kk][ty * 8 + 4];
            float4 b0 = *(const float4*)&Bs[kk][tx * 8];
            float4 b1 = *(const float4*)&Bs[kk][tx * 8 + 4];
            float a[8] = {a0.x, a0.y, a0.z, a0.w, a1.x, a1.y, a1.z, a1.w};
            float b[8] = {b0.x, b0.y, b0.z, b0.w, b1.x, b1.y, b1.z, b1.w};
#pragma unroll
            for (int i = 0; i < 8; i++)
#pragma unroll
                for (int j = 0; j < 8; j++) acc[i][j] += a[i] * b[j];
        }
    }

#pragma unroll
    for (int i = 0; i < 8; i++) {
        float4 v0 = make_float4(acc[i][0], acc[i][1], acc[i][2], acc[i][3]);
        float4 v1 = make_float4(acc[i][4], acc[i][5], acc[i][6], acc[i][7]);
        size_t crow = (size_t)(bm + ty * 8 + i) * N + bn + tx * 8;
        *(float4*)&C[crow]     = v0;
        *(float4*)&C[crow + 4] = v1;
    }
}

__global__ __launch_bounds__(256) void sgemm_nt(const float* __restrict__ A,
                                                const float* __restrict__ B,
                                                float* __restrict__ C) {
    sgemm_nt_body(A, B, C, D_MODEL, D_MODEL);
}

// Fused QKV: blockIdx.z selects which projection. x tiles reuse L2 across z.
__global__ __launch_bounds__(256) void sgemm_qkv(const float* __restrict__ x,
                                                 const float* __restrict__ wq,
                                                 const float* __restrict__ wk,
                                                 const float* __restrict__ wv,
                                                 float* __restrict__ q,
                                                 float* __restrict__ k,
                                                 float* __restrict__ v) {
    const float* B = (blockIdx.z == 0) ? wq : (blockIdx.z == 1) ? wk : wv;
    float*       C = (blockIdx.z == 0) ? q  : (blockIdx.z == 1) ? k  : v;
    sgemm_nt_body(x, B, C, D_MODEL, D_MODEL);
}

// ---------------------------------------------------------------------------
// RoPE in-place on q and k. One thread per (row, pair).
// ---------------------------------------------------------------------------
__global__ void rope_kernel(float* __restrict__ q, float* __restrict__ k) {
    int idx = blockIdx.x * blockDim.x + threadIdx.x;
    if (idx >= MTOK * (D_MODEL / 2)) return;
    int col2 = idx & 511;        // pair index within row (D_MODEL/2 = 512)
    int row  = idx >> 9;
    int d    = col2 & 31;        // pair index within head (half = 32)
    int s    = row & (SEQ - 1);  // position in sequence
    // inv_freq = 10000^(-d/32) = 2^(-d * log2(10000)/32)
    float inv = exp2f(-(float)d * (13.2877123795494935f / 32.0f));
    float ang = (float)s * inv;
    float sn, cs;
    sincosf(ang, &sn, &cs);
    size_t i = (size_t)row * D_MODEL + (size_t)col2 * 2;
    float2 qv = *(float2*)&q[i];
    float2 kv = *(float2*)&k[i];
    *(float2*)&q[i] = make_float2(qv.x * cs - qv.y * sn, qv.x * sn + qv.y * cs);
    *(float2*)&k[i] = make_float2(kv.x * cs - kv.y * sn, kv.x * sn + kv.y * cs);
}

// ---------------------------------------------------------------------------
// Flash attention (fp32, causal + padding mask).
// Block = (q-tile 64 rows, head, batch). 256 threads: 4 threads per q-row,
// each owning 16 score columns / 16 output dims. P exchanged via shuffles
// (the 4 row-sibling threads are always in the same warp).
// ---------------------------------------------------------------------------
#define FL_SMEM (3 * 64 * 66 * 4)   // Qs, Ks, Vs with pitch 66 -> 50688 B

__global__ __launch_bounds__(256) void flash_kernel(const float* __restrict__ q,
                                                    const float* __restrict__ k,
                                                    const float* __restrict__ v,
                                                    const int* __restrict__ mask,
                                                    float* __restrict__ ctx) {
    extern __shared__ float sm[];
    float* Qs = sm;               // [64][66]
    float* Ks = sm + 64 * 66;     // [64][66]
    float* Vs = sm + 2 * 64 * 66; // [64][66]

    const int qt  = blockIdx.x;
    const int h   = blockIdx.y;
    const int b   = blockIdx.z;
    const int tid = threadIdx.x;
    const int r   = tid >> 2;     // q row within tile
    const int sub = tid & 3;
    const int c0  = sub * 16;
    const int sq  = qt * 64 + r;  // absolute q position
    const size_t base_row = (size_t)b * SEQ;

    // Load Q tile (pre-scaled by 1/sqrt(DK))
    for (int rr = 0; rr < 16; rr++) {
        int idx  = rr * 256 + tid;
        int rowi = idx >> 6, col = idx & 63;
        Qs[rowi * 66 + col] =
            q[(base_row + qt * 64 + rowi) * D_MODEL + h * DK + col] * 0.125f;
    }

    float m_run = -1e30f, l_run = 0.f;
    float o[16];
#pragma unroll
    for (int j = 0; j < 16; j++) o[j] = 0.f;

    for (int kt = 0; kt <= qt; kt++) {
        __syncthreads();  // prior iter's reads of Ks/Vs done; Qs visible (1st iter)
        for (int rr = 0; rr < 16; rr++) {
            int idx  = rr * 256 + tid;
            int rowi = idx >> 6, col = idx & 63;
            size_t g = (base_row + kt * 64 + rowi) * D_MODEL + h * DK + col;
            Ks[rowi * 66 + col] = k[g];
            Vs[rowi * 66 + col] = v[g];
        }
        __syncthreads();

        // Scores: s[j] = Q[r] . K[c0+j]
        float s[16];
#pragma unroll
        for (int j = 0; j < 16; j++) s[j] = 0.f;
#pragma unroll 8
        for (int kk = 0; kk < 64; kk++) {
            float qv = Qs[r * 66 + kk];
#pragma unroll
            for (int j = 0; j < 16; j++) s[j] += qv * Ks[(c0 + j) * 66 + kk];
        }

        // Causal + padding mask
#pragma unroll
        for (int j = 0; j < 16; j++) {
            int ck = kt * 64 + c0 + j;
            if (ck > sq || mask[base_row + ck] == 0) s[j] = -1e9f;
        }

        // Row max across this thread's 16 cols + the 4 sibling threads
        float mt = s[0];
#pragma unroll
        for (int j = 1; j < 16; j++) mt = fmaxf(mt, s[j]);
        mt = fmaxf(mt, __shfl_xor_sync(0xffffffffu, mt, 1));
        mt = fmaxf(mt, __shfl_xor_sync(0xffffffffu, mt, 2));
        float m_new = fmaxf(m_run, mt);

        float p[16];
        float lt = 0.f;
#pragma unroll
        for (int j = 0; j < 16; j++) {
            p[j] = __expf(s[j] - m_new);
            lt += p[j];
        }
        lt += __shfl_xor_sync(0xffffffffu, lt, 1);
        lt += __shfl_xor_sync(0xffffffffu, lt, 2);

        float alpha = __expf(m_run - m_new);
        l_run = l_run * alpha + lt;
        m_run = m_new;
#pragma unroll
        for (int j = 0; j < 16; j++) o[j] *= alpha;

        // O += P @ V.  P row lives in registers across the 4 sibling lanes:
        // lane owning kk is (lane & ~3) | (kk >> 4); exchange via shuffle.
        const int lane_base = (tid & 31) & ~3;
#pragma unroll 4
        for (int kq = 0; kq < 4; kq++) {          // which sibling owns this chunk
            int src = lane_base + kq;
#pragma unroll
            for (int kj = 0; kj < 16; kj++) {
                float pv = __shfl_sync(0xffffffffu, p[kj], src);
                int kk = kq * 16 + kj;
#pragma unroll
                for (int j = 0; j < 16; j++) o[j] += pv * Vs[kk * 66 + c0 + j];
            }
        }
    }

    float invl = 1.f / l_run;
#pragma unroll
    for (int j = 0; j < 16; j++)
        ctx[(base_row + qt * 64 + r) * D_MODEL + h * DK + c0 + j] = o[j] * invl;
}

// ---------------------------------------------------------------------------
extern "C" void kernel_launch(void* const* d_in, const int* in_sizes, int n_in,
                              void* d_out, int out_size) {
    const float* x  = (const float*)d_in[0];
    const int*   am = (const int*)d_in[1];
    const float* wq = (const float*)d_in[2];
    const float* wk = (const float*)d_in[3];
    const float* wv = (const float*)d_in[4];
    const float* wo = (const float*)d_in[5];

    float *q, *k, *v, *ctx;
    cudaGetSymbolAddress((void**)&q,   g_q);
    cudaGetSymbolAddress((void**)&k,   g_k);
    cudaGetSymbolAddress((void**)&v,   g_v);
    cudaGetSymbolAddress((void**)&ctx, g_ctx);

    dim3 gg(D_MODEL / 128, MTOK / 128, 3);  // (8, 32, 3)
    sgemm_qkv<<<gg, 256>>>(x, wq, wk, wv, q, k, v);

    rope_kernel<<<(MTOK * (D_MODEL / 2)) / 256, 256>>>(q, k);

    cudaFuncSetAttribute(flash_kernel,
                         cudaFuncAttributeMaxDynamicSharedMemorySize, FL_SMEM);
    flash_kernel<<<dim3(SEQ / 64, HEADS, BATCH), 256, FL_SMEM>>>(q, k, v, am, ctx);

    dim3 go(D_MODEL / 128, MTOK / 128);
    sgemm_nt<<<go, 256>>>(ctx, wo, (float*)d_out);
}

// round 3
// speedup vs baseline: 1.0005x; 1.0005x over previous
#include <cuda_runtime.h>
#include <cstdint>

#define D_MODEL 1024
#define HEADS   16
#define DK      64
#define BATCH   2
#define SEQ     2048
#define MTOK    (BATCH * SEQ)   // 4096

// Scratch (allocation-free: static device globals)
__device__ float g_q[(size_t)MTOK * D_MODEL];
__device__ float g_k[(size_t)MTOK * D_MODEL];
__device__ float g_v[(size_t)MTOK * D_MODEL];
__device__ float g_ctx[(size_t)MTOK * D_MODEL];

// ---------------------------------------------------------------------------
// C[m][n] = sum_k A[m][k] * B[n][k]   (A: MxK row-major, B: NxK row-major)
// 128x128 block tile, BK=8, 256 threads, 8x8 per-thread micro-tile.
// ---------------------------------------------------------------------------
__device__ __forceinline__ void sgemm_nt_body(const float* __restrict__ A,
                                              const float* __restrict__ B,
                                              float* __restrict__ C,
                                              int K, int N) {
    __shared__ __align__(16) float As[8][128];
    __shared__ __align__(16) float Bs[8][128];

    const int tid  = threadIdx.x;
    const int bm   = blockIdx.y * 128;
    const int bn   = blockIdx.x * 128;
    const int lrow = tid >> 1;          // 0..127
    const int lcol = (tid & 1) * 4;     // 0 or 4
    const int tx   = tid & 15;
    const int ty   = tid >> 4;

    const float* Ap = A + (size_t)(bm + lrow) * K + lcol;
    const float* Bp = B + (size_t)(bn + lrow) * K + lcol;

    float acc[8][8];
#pragma unroll
    for (int i = 0; i < 8; i++)
#pragma unroll
        for (int j = 0; j < 8; j++) acc[i][j] = 0.f;

    for (int k0 = 0; k0 < K; k0 += 8) {
        float4 av = *(const float4*)(Ap + k0);
        float4 bv = *(const float4*)(Bp + k0);
        __syncthreads();
        As[lcol + 0][lrow] = av.x;
        As[lcol + 1][lrow] = av.y;
        As[lcol + 2][lrow] = av.z;
        As[lcol + 3][lrow] = av.w;
        Bs[lcol + 0][lrow] = bv.x;
        Bs[lcol + 1][lrow] = bv.y;
        Bs[lcol + 2][lrow] = bv.z;
        Bs[lcol + 3][lrow] = bv.w;
        __syncthreads();
#pragma unroll
        for (int kk = 0; kk < 8; kk++) {
            float4 a0 = *(const float4*)&As[kk][ty * 8];
            float4 a1 = *(const float4*)&As[kk][ty * 8 + 4];
            float4 b0 = *(const float4*)&Bs[kk][tx * 8];
            float4 b1 = *(const float4*)&Bs[kk][tx * 8 + 4];
            float a[8] = {a0.x, a0.y, a0.z, a0.w, a1.x, a1.y, a1.z, a1.w};
            float b[8] = {b0.x, b0.y, b0.z, b0.w, b1.x, b1.y, b1.z, b1.w};
#pragma unroll
            for (int i = 0; i < 8; i++)
#pragma unroll
                for (int j = 0; j < 8; j++) acc[i][j] += a[i] * b[j];
        }
    }

#pragma unroll
    for (int i = 0; i < 8; i++) {
        float4 v0 = make_float4(acc[i][0], acc[i][1], acc[i][2], acc[i][3]);
        float4 v1 = make_float4(acc[i][4], acc[i][5], acc[i][6], acc[i][7]);
        size_t crow = (size_t)(bm + ty * 8 + i) * N + bn + tx * 8;
        *(float4*)&C[crow]     = v0;
        *(float4*)&C[crow + 4] = v1;
    }
}

__global__ __launch_bounds__(256) void sgemm_nt(const float* __restrict__ A,
                                                const float* __restrict__ B,
                                                float* __restrict__ C) {
    sgemm_nt_body(A, B, C, D_MODEL, D_MODEL);
}

// Fused QKV: blockIdx.z selects which projection. x tiles reuse L2 across z.
__global__ __launch_bounds__(256) void sgemm_qkv(const float* __restrict__ x,
                                                 const float* __restrict__ wq,
                                                 const float* __restrict__ wk,
                                                 const float* __restrict__ wv,
                                                 float* __restrict__ q,
                                                 float* __restrict__ k,
                                                 float* __restrict__ v) {
    const float* B = (blockIdx.z == 0) ? wq : (blockIdx.z == 1) ? wk : wv;
    float*       C = (blockIdx.z == 0) ? q  : (blockIdx.z == 1) ? k  : v;
    sgemm_nt_body(x, B, C, D_MODEL, D_MODEL);
}

// ---------------------------------------------------------------------------
// RoPE in-place on q and k. One thread per (row, pair).
// ---------------------------------------------------------------------------
__global__ void rope_kernel(float* __restrict__ q, float* __restrict__ k) {
    int idx = blockIdx.x * blockDim.x + threadIdx.x;
    if (idx >= MTOK * (D_MODEL / 2)) return;
    int col2 = idx & 511;        // pair index within row (D_MODEL/2 = 512)
    int row  = idx >> 9;
    int d    = col2 & 31;        // pair index within head (half = 32)
    int s    = row & (SEQ - 1);  // position in sequence
    // inv_freq = 10000^(-d/32) = 2^(-d * log2(10000)/32)
    float inv = exp2f(-(float)d * (13.2877123795494935f / 32.0f));
    float ang = (float)s * inv;
    float sn, cs;
    sincosf(ang, &sn, &cs);
    size_t i = (size_t)row * D_MODEL + (size_t)col2 * 2;
    float2 qv = *(float2*)&q[i];
    float2 kv = *(float2*)&k[i];
    *(float2*)&q[i] = make_float2(qv.x * cs - qv.y * sn, qv.x * sn + qv.y * cs);
    *(float2*)&k[i] = make_float2(kv.x * cs - kv.y * sn, kv.x * sn + kv.y * cs);
}

// ---------------------------------------------------------------------------
// Flash attention (fp32, causal + padding mask).
// Block = (q-tile 64 rows, head, batch). 256 threads: 4 threads per q-row,
// each owning 16 score columns / 16 output dims. P exchanged via shuffles
// (the 4 row-sibling threads are always in the same warp).
// ---------------------------------------------------------------------------
#define FL_SMEM (3 * 64 * 66 * 4)   // Qs, Ks, Vs with pitch 66 -> 50688 B

__global__ __launch_bounds__(256) void flash_kernel(const float* __restrict__ q,
                                                    const float* __restrict__ k,
                                                    const float* __restrict__ v,
                                                    const int* __restrict__ mask,
                                                    float* __restrict__ ctx) {
    extern __shared__ float sm[];
    float* Qs = sm;               // [64][66]
    float* Ks = sm + 64 * 66;     // [64][66]
    float* Vs = sm + 2 * 64 * 66; // [64][66]

    const int qt  = blockIdx.x;
    const int h   = blockIdx.y;
    const int b   = blockIdx.z;
    const int tid = threadIdx.x;
    const int r   = tid >> 2;     // q row within tile
    const int sub = tid & 3;
    const int c0  = sub * 16;
    const int sq  = qt * 64 + r;  // absolute q position
    const size_t base_row = (size_t)b * SEQ;

    // Load Q tile (pre-scaled by 1/sqrt(DK))
    for (int rr = 0; rr < 16; rr++) {
        int idx  = rr * 256 + tid;
        int rowi = idx >> 6, col = idx & 63;
        Qs[rowi * 66 + col] =
            q[(base_row + qt * 64 + rowi) * D_MODEL + h * DK + col] * 0.125f;
    }

    float m_run = -1e30f, l_run = 0.f;
    float o[16];
#pragma unroll
    for (int j = 0; j < 16; j++) o[j] = 0.f;

    for (int kt = 0; kt <= qt; kt++) {
        __syncthreads();  // prior iter's reads of Ks/Vs done; Qs visible (1st iter)
        for (int rr = 0; rr < 16; rr++) {
            int idx  = rr * 256 + tid;
            int rowi = idx >> 6, col = idx & 63;
            size_t g = (base_row + kt * 64 + rowi) * D_MODEL + h * DK + col;
            Ks[rowi * 66 + col] = k[g];
            Vs[rowi * 66 + col] = v[g];
        }
        __syncthreads();

        // Scores: s[j] = Q[r] . K[c0+j]
        float s[16];
#pragma unroll
        for (int j = 0; j < 16; j++) s[j] = 0.f;
#pragma unroll 8
        for (int kk = 0; kk < 64; kk++) {
            float qv = Qs[r * 66 + kk];
#pragma unroll
            for (int j = 0; j < 16; j++) s[j] += qv * Ks[(c0 + j) * 66 + kk];
        }

        // Causal + padding mask
#pragma unroll
        for (int j = 0; j < 16; j++) {
            int ck = kt * 64 + c0 + j;
            if (ck > sq || mask[base_row + ck] == 0) s[j] = -1e9f;
        }

        // Row max across this thread's 16 cols + the 4 sibling threads
        float mt = s[0];
#pragma unroll
        for (int j = 1; j < 16; j++) mt = fmaxf(mt, s[j]);
        mt = fmaxf(mt, __shfl_xor_sync(0xffffffffu, mt, 1));
        mt = fmaxf(mt, __shfl_xor_sync(0xffffffffu, mt, 2));
        float m_new = fmaxf(m_run, mt);

        float p[16];
        float lt = 0.f;
#pragma unroll
        for (int j = 0; j < 16; j++) {
            p[j] = __expf(s[j] - m_new);
            lt += p[j];
        }
        lt += __shfl_xor_sync(0xffffffffu, lt, 1);
        lt += __shfl_xor_sync(0xffffffffu, lt, 2);

        float alpha = __expf(m_run - m_new);
        l_run = l_run * alpha + lt;
        m_run = m_new;
#pragma unroll
        for (int j = 0; j < 16; j++) o[j] *= alpha;

        // O += P @ V.  P row lives in registers across the 4 sibling lanes:
        // lane owning kk is (lane & ~3) | (kk >> 4); exchange via shuffle.
        const int lane_base = (tid & 31) & ~3;
#pragma unroll 4
        for (int kq = 0; kq < 4; kq++) {          // which sibling owns this chunk
            int src = lane_base + kq;
#pragma unroll
            for (int kj = 0; kj < 16; kj++) {
                float pv = __shfl_sync(0xffffffffu, p[kj], src);
                int kk = kq * 16 + kj;
#pragma unroll
                for (int j = 0; j < 16; j++) o[j] += pv * Vs[kk * 66 + c0 + j];
            }
        }
    }

    float invl = 1.f / l_run;
#pragma unroll
    for (int j = 0; j < 16; j++)
        ctx[(base_row + qt * 64 + r) * D_MODEL + h * DK + c0 + j] = o[j] * invl;
}

// ---------------------------------------------------------------------------
extern "C" void kernel_launch(void* const* d_in, const int* in_sizes, int n_in,
                              void* d_out, int out_size) {
    const float* x  = (const float*)d_in[0];
    const int*   am = (const int*)d_in[1];
    const float* wq = (const float*)d_in[2];
    const float* wk = (const float*)d_in[3];
    const float* wv = (const float*)d_in[4];
    const float* wo = (const float*)d_in[5];

    float *q, *k, *v, *ctx;
    cudaGetSymbolAddress((void**)&q,   g_q);
    cudaGetSymbolAddress((void**)&k,   g_k);
    cudaGetSymbolAddress((void**)&v,   g_v);
    cudaGetSymbolAddress((void**)&ctx, g_ctx);

    dim3 gg(D_MODEL / 128, MTOK / 128, 3);  // (8, 32, 3)
    sgemm_qkv<<<gg, 256>>>(x, wq, wk, wv, q, k, v);

    rope_kernel<<<(MTOK * (D_MODEL / 2)) / 256, 256>>>(q, k);

    cudaFuncSetAttribute(flash_kernel,
                         cudaFuncAttributeMaxDynamicSharedMemorySize, FL_SMEM);
    flash_kernel<<<dim3(SEQ / 64, HEADS, BATCH), 256, FL_SMEM>>>(q, k, v, am, ctx);

    dim3 go(D_MODEL / 128, MTOK / 128);
    sgemm_nt<<<go, 256>>>(ctx, wo, (float*)d_out);
}

// round 5
// speedup vs baseline: 7.2564x; 7.2529x over previous
#include <cuda_runtime.h>
#include <cstdint>

#define D_MODEL 1024
#define HEADS   16
#define DK      64
#define BATCH   2
#define SEQ     2048
#define MTOK    (BATCH * SEQ)   // 4096
#define NEGV    -1e9f

// Scratch (allocation-free: static device globals)
__device__ float g_q[(size_t)MTOK * D_MODEL];
__device__ float g_k[(size_t)MTOK * D_MODEL];
__device__ float g_v[(size_t)MTOK * D_MODEL];
__device__ float g_ctx[(size_t)MTOK * D_MODEL];

// ---------------------------------------------------------------------------
// tf32 helpers
// ---------------------------------------------------------------------------
__device__ __forceinline__ unsigned f2tf(float x) {
    unsigned r;
    asm("cvt.rna.tf32.f32 %0, %1;" : "=r"(r) : "f"(x));
    return r;
}
__device__ __forceinline__ float f2tf_f(float x) { return __uint_as_float(f2tf(x)); }

// D += A(16x8) * B(8x8), tf32 inputs, fp32 accum.
__device__ __forceinline__ void mma8(float* c, const unsigned* a, unsigned b0, unsigned b1) {
    asm volatile(
        "mma.sync.aligned.m16n8k8.row.col.f32.tf32.tf32.f32 "
        "{%0,%1,%2,%3},{%4,%5,%6,%7},{%8,%9},{%0,%1,%2,%3};"
        : "+f"(c[0]), "+f"(c[1]), "+f"(c[2]), "+f"(c[3])
        : "r"(a[0]), "r"(a[1]), "r"(a[2]), "r"(a[3]), "r"(b0), "r"(b1));
}

// ---------------------------------------------------------------------------
// tf32 GEMM: C[m][n] = sum_k A[m][k] * B[n][k]  (NT, both row-major K-contig)
// 128x128 tile, BK=16, 256 threads = 8 warps (2m x 4n), each warp 64x32.
// Smem stored K-major with word-stride 136 -> all fragment loads conflict-free.
// ---------------------------------------------------------------------------
#define GSTR 136

__device__ __forceinline__ void gemm_tf32_body(const float* __restrict__ A,
                                               const float* __restrict__ B,
                                               float* __restrict__ C) {
    __shared__ float As[16 * GSTR];
    __shared__ float Bs[16 * GSTR];

    const int tid  = threadIdx.x;
    const int lane = tid & 31;
    const int wid  = tid >> 5;
    const int g    = lane >> 2;   // group 0..7
    const int tg   = lane & 3;    // 0..3
    const int wm   = wid & 1;     // warp m 0..1 (64 rows each)
    const int wn   = wid >> 1;    // warp n 0..3 (32 cols each)
    const int bm   = blockIdx.y * 128;
    const int bn   = blockIdx.x * 128;

    const int lrow = tid >> 1;          // 0..127
    const int lk   = (tid & 1) * 8;     // 0 or 8

    const float* Ap = A + (size_t)(bm + lrow) * D_MODEL + lk;
    const float* Bp = B + (size_t)(bn + lrow) * D_MODEL + lk;

    float cf[4][4][4];
#pragma unroll
    for (int mt = 0; mt < 4; mt++)
#pragma unroll
        for (int nt = 0; nt < 4; nt++)
#pragma unroll
            for (int j = 0; j < 4; j++) cf[mt][nt][j] = 0.f;

    for (int k0 = 0; k0 < D_MODEL; k0 += 16) {
        float4 a0 = *(const float4*)(Ap + k0);
        float4 a1 = *(const float4*)(Ap + k0 + 4);
        float4 b0 = *(const float4*)(Bp + k0);
        float4 b1 = *(const float4*)(Bp + k0 + 4);
        __syncthreads();
        As[(lk + 0) * GSTR + lrow] = f2tf_f(a0.x);
        As[(lk + 1) * GSTR + lrow] = f2tf_f(a0.y);
        As[(lk + 2) * GSTR + lrow] = f2tf_f(a0.z);
        As[(lk + 3) * GSTR + lrow] = f2tf_f(a0.w);
        As[(lk + 4) * GSTR + lrow] = f2tf_f(a1.x);
        As[(lk + 5) * GSTR + lrow] = f2tf_f(a1.y);
        As[(lk + 6) * GSTR + lrow] = f2tf_f(a1.z);
        As[(lk + 7) * GSTR + lrow] = f2tf_f(a1.w);
        Bs[(lk + 0) * GSTR + lrow] = f2tf_f(b0.x);
        Bs[(lk + 1) * GSTR + lrow] = f2tf_f(b0.y);
        Bs[(lk + 2) * GSTR + lrow] = f2tf_f(b0.z);
        Bs[(lk + 3) * GSTR + lrow] = f2tf_f(b0.w);
        Bs[(lk + 4) * GSTR + lrow] = f2tf_f(b1.x);
        Bs[(lk + 5) * GSTR + lrow] = f2tf_f(b1.y);
        Bs[(lk + 6) * GSTR + lrow] = f2tf_f(b1.z);
        Bs[(lk + 7) * GSTR + lrow] = f2tf_f(b1.w);
        __syncthreads();

#pragma unroll
        for (int kb = 0; kb < 16; kb += 8) {
            unsigned af[4][4];
#pragma unroll
            for (int mt = 0; mt < 4; mt++) {
                int m = wm * 64 + mt * 16 + g;
                af[mt][0] = __float_as_uint(As[(kb + tg) * GSTR + m]);
                af[mt][1] = __float_as_uint(As[(kb + tg) * GSTR + m + 8]);
                af[mt][2] = __float_as_uint(As[(kb + tg + 4) * GSTR + m]);
                af[mt][3] = __float_as_uint(As[(kb + tg + 4) * GSTR + m + 8]);
            }
#pragma unroll
            for (int nt = 0; nt < 4; nt++) {
                int n = wn * 32 + nt * 8 + g;
                unsigned bb0 = __float_as_uint(Bs[(kb + tg) * GSTR + n]);
                unsigned bb1 = __float_as_uint(Bs[(kb + tg + 4) * GSTR + n]);
#pragma unroll
                for (int mt = 0; mt < 4; mt++) mma8(cf[mt][nt], af[mt], bb0, bb1);
            }
        }
    }

#pragma unroll
    for (int mt = 0; mt < 4; mt++) {
        int m0 = bm + wm * 64 + mt * 16 + g;
#pragma unroll
        for (int nt = 0; nt < 4; nt++) {
            int n0 = bn + wn * 32 + nt * 8 + 2 * tg;
            *(float2*)&C[(size_t)m0 * D_MODEL + n0] =
                make_float2(cf[mt][nt][0], cf[mt][nt][1]);
            *(float2*)&C[(size_t)(m0 + 8) * D_MODEL + n0] =
                make_float2(cf[mt][nt][2], cf[mt][nt][3]);
        }
    }
}

__global__ __launch_bounds__(256) void gemm_out(const float* __restrict__ A,
                                                const float* __restrict__ B,
                                                float* __restrict__ C) {
    gemm_tf32_body(A, B, C);
}

__global__ __launch_bounds__(256) void gemm_qkv(const float* __restrict__ x,
                                                const float* __restrict__ wq,
                                                const float* __restrict__ wk,
                                                const float* __restrict__ wv,
                                                float* __restrict__ q,
                                                float* __restrict__ k,
                                                float* __restrict__ v) {
    const float* B = (blockIdx.z == 0) ? wq : (blockIdx.z == 1) ? wk : wv;
    float*       C = (blockIdx.z == 0) ? q  : (blockIdx.z == 1) ? k  : v;
    gemm_tf32_body(x, B, C);
}

// ---------------------------------------------------------------------------
// RoPE in-place on q and k.
// ---------------------------------------------------------------------------
__global__ void rope_kernel(float* __restrict__ q, float* __restrict__ k) {
    int idx = blockIdx.x * blockDim.x + threadIdx.x;
    if (idx >= MTOK * (D_MODEL / 2)) return;
    int col2 = idx & 511;
    int row  = idx >> 9;
    int d    = col2 & 31;
    int s    = row & (SEQ - 1);
    float inv = exp2f(-(float)d * (13.2877123795494935f / 32.0f));
    float ang = (float)s * inv;
    float sn, cs;
    sincosf(ang, &sn, &cs);
    size_t i = (size_t)row * D_MODEL + (size_t)col2 * 2;
    float2 qv = *(float2*)&q[i];
    float2 kv = *(float2*)&k[i];
    *(float2*)&q[i] = make_float2(qv.x * cs - qv.y * sn, qv.x * sn + qv.y * cs);
    *(float2*)&k[i] = make_float2(kv.x * cs - kv.y * sn, kv.x * sn + kv.y * cs);
}

// ---------------------------------------------------------------------------
// Flash attention, tf32 tensor cores. 64x64 tiles, 128 threads = 4 warps,
// each warp owns 16 q rows. QK^T and PV via mma.m16n8k8; P goes through a
// per-warp smem slab (same-warp producer/consumer -> __syncwarp only).
// Smem word-stride 68: all fragment load patterns are bank-conflict-free.
// ---------------------------------------------------------------------------
#define FSTR 68
#define FL_SMEM (4 * 64 * FSTR * 4)   // Qs, Ks, Vs, Ps = 69632 B

__global__ __launch_bounds__(128) void flash_mma(const float* __restrict__ q,
                                                 const float* __restrict__ k,
                                                 const float* __restrict__ v,
                                                 const int* __restrict__ mask,
                                                 float* __restrict__ ctx) {
    extern __shared__ float sm[];
    float* Qs = sm;
    float* Ks = sm + 64 * FSTR;
    float* Vs = sm + 2 * 64 * FSTR;
    float* Ps = sm + 3 * 64 * FSTR;

    const int qt   = blockIdx.x;
    const int h    = blockIdx.y;
    const int b    = blockIdx.z;
    const int tid  = threadIdx.x;
    const int lane = tid & 31;
    const int wid  = tid >> 5;
    const int g    = lane >> 2;
    const int tg   = lane & 3;
    const int wrow = wid * 16;
    const size_t base = (size_t)b * SEQ;

    // Load Q tile, scaled by 1/sqrt(DK), tf32-rounded.
#pragma unroll
    for (int it = 0; it < 8; it++) {
        int i    = it * 128 + tid;      // 0..1023 float4 slots
        int row  = i >> 4;
        int col4 = (i & 15) * 4;
        float4 t = *(const float4*)&q[(base + qt * 64 + row) * D_MODEL + h * DK + col4];
        Qs[row * FSTR + col4 + 0] = f2tf_f(t.x * 0.125f);
        Qs[row * FSTR + col4 + 1] = f2tf_f(t.y * 0.125f);
        Qs[row * FSTR + col4 + 2] = f2tf_f(t.z * 0.125f);
        Qs[row * FSTR + col4 + 3] = f2tf_f(t.w * 0.125f);
    }

    float m_lo = -1e30f, m_hi = -1e30f, l_lo = 0.f, l_hi = 0.f;
    float of[8][4];
#pragma unroll
    for (int nt = 0; nt < 8; nt++)
#pragma unroll
        for (int j = 0; j < 4; j++) of[nt][j] = 0.f;

    for (int kt = 0; kt <= qt; kt++) {
        __syncthreads();  // prior iter's Ks/Vs reads done; Qs visible (1st iter)
#pragma unroll
        for (int it = 0; it < 8; it++) {
            int i    = it * 128 + tid;
            int row  = i >> 4;
            int col4 = (i & 15) * 4;
            size_t gidx = (base + kt * 64 + row) * D_MODEL + h * DK + col4;
            float4 tk = *(const float4*)&k[gidx];
            float4 tv = *(const float4*)&v[gidx];
            Ks[row * FSTR + col4 + 0] = f2tf_f(tk.x);
            Ks[row * FSTR + col4 + 1] = f2tf_f(tk.y);
            Ks[row * FSTR + col4 + 2] = f2tf_f(tk.z);
            Ks[row * FSTR + col4 + 3] = f2tf_f(tk.w);
            Vs[row * FSTR + col4 + 0] = f2tf_f(tv.x);
            Vs[row * FSTR + col4 + 1] = f2tf_f(tv.y);
            Vs[row * FSTR + col4 + 2] = f2tf_f(tv.z);
            Vs[row * FSTR + col4 + 3] = f2tf_f(tv.w);
        }
        __syncthreads();

        // ---- S = Q . K^T ----
        unsigned af[8][4];
#pragma unroll
        for (int kc = 0; kc < 8; kc++) {
            af[kc][0] = __float_as_uint(Qs[(wrow + g) * FSTR + kc * 8 + tg]);
            af[kc][1] = __float_as_uint(Qs[(wrow + g + 8) * FSTR + kc * 8 + tg]);
            af[kc][2] = __float_as_uint(Qs[(wrow + g) * FSTR + kc * 8 + tg + 4]);
            af[kc][3] = __float_as_uint(Qs[(wrow + g + 8) * FSTR + kc * 8 + tg + 4]);
        }
        float sf[8][4];
#pragma unroll
        for (int nt = 0; nt < 8; nt++) {
#pragma unroll
            for (int j = 0; j < 4; j++) sf[nt][j] = 0.f;
#pragma unroll
            for (int kc = 0; kc < 8; kc++) {
                unsigned bb0 = __float_as_uint(Ks[(nt * 8 + g) * FSTR + kc * 8 + tg]);
                unsigned bb1 = __float_as_uint(Ks[(nt * 8 + g) * FSTR + kc * 8 + tg + 4]);
                mma8(sf[nt], af[kc], bb0, bb1);
            }
        }

        // ---- masks ----
#pragma unroll
        for (int nt = 0; nt < 8; nt++) {
            int colg = kt * 64 + nt * 8 + 2 * tg;
            if (mask[base + colg] == 0)     { sf[nt][0] = NEGV; sf[nt][2] = NEGV; }
            if (mask[base + colg + 1] == 0) { sf[nt][1] = NEGV; sf[nt][3] = NEGV; }
        }
        if (kt == qt) {
#pragma unroll
            for (int nt = 0; nt < 8; nt++) {
                int c    = nt * 8 + 2 * tg;
                int r_lo = wrow + g;
                int r_hi = r_lo + 8;
                if (c > r_lo)     sf[nt][0] = NEGV;
                if (c + 1 > r_lo) sf[nt][1] = NEGV;
                if (c > r_hi)     sf[nt][2] = NEGV;
                if (c + 1 > r_hi) sf[nt][3] = NEGV;
            }
        }

        // ---- online softmax ----
        float mt_lo = sf[0][0], mt_hi = sf[0][2];
#pragma unroll
        for (int nt = 0; nt < 8; nt++) {
            mt_lo = fmaxf(mt_lo, fmaxf(sf[nt][0], sf[nt][1]));
            mt_hi = fmaxf(mt_hi, fmaxf(sf[nt][2], sf[nt][3]));
        }
        mt_lo = fmaxf(mt_lo, __shfl_xor_sync(0xffffffffu, mt_lo, 1));
        mt_lo = fmaxf(mt_lo, __shfl_xor_sync(0xffffffffu, mt_lo, 2));
        mt_hi = fmaxf(mt_hi, __shfl_xor_sync(0xffffffffu, mt_hi, 1));
        mt_hi = fmaxf(mt_hi, __shfl_xor_sync(0xffffffffu, mt_hi, 2));
        float mn_lo = fmaxf(m_lo, mt_lo);
        float mn_hi = fmaxf(m_hi, mt_hi);

        float lt_lo = 0.f, lt_hi = 0.f;
#pragma unroll
        for (int nt = 0; nt < 8; nt++) {
            sf[nt][0] = __expf(sf[nt][0] - mn_lo);
            sf[nt][1] = __expf(sf[nt][1] - mn_lo);
            sf[nt][2] = __expf(sf[nt][2] - mn_hi);
            sf[nt][3] = __expf(sf[nt][3] - mn_hi);
            lt_lo += sf[nt][0] + sf[nt][1];
            lt_hi += sf[nt][2] + sf[nt][3];
        }
        lt_lo += __shfl_xor_sync(0xffffffffu, lt_lo, 1);
        lt_lo += __shfl_xor_sync(0xffffffffu, lt_lo, 2);
        lt_hi += __shfl_xor_sync(0xffffffffu, lt_hi, 1);
        lt_hi += __shfl_xor_sync(0xffffffffu, lt_hi, 2);

        float a_lo = __expf(m_lo - mn_lo);
        float a_hi = __expf(m_hi - mn_hi);
        l_lo = l_lo * a_lo + lt_lo;
        l_hi = l_hi * a_hi + lt_hi;
        m_lo = mn_lo;
        m_hi = mn_hi;
#pragma unroll
        for (int nt = 0; nt < 8; nt++) {
            of[nt][0] *= a_lo;
            of[nt][1] *= a_lo;
            of[nt][2] *= a_hi;
            of[nt][3] *= a_hi;
        }

        // ---- P -> per-warp smem slab (tf32) ----
#pragma unroll
        for (int nt = 0; nt < 8; nt++) {
            int pidx = (wrow + g) * FSTR + nt * 8 + 2 * tg;
            *(float2*)&Ps[pidx] = make_float2(f2tf_f(sf[nt][0]), f2tf_f(sf[nt][1]));
            *(float2*)&Ps[pidx + 8 * FSTR] = make_float2(f2tf_f(sf[nt][2]), f2tf_f(sf[nt][3]));
        }
        __syncwarp();

        // ---- O += P . V ----
#pragma unroll
        for (int kc = 0; kc < 8; kc++) {
            af[kc][0] = __float_as_uint(Ps[(wrow + g) * FSTR + kc * 8 + tg]);
            af[kc][1] = __float_as_uint(Ps[(wrow + g + 8) * FSTR + kc * 8 + tg]);
            af[kc][2] = __float_as_uint(Ps[(wrow + g) * FSTR + kc * 8 + tg + 4]);
            af[kc][3] = __float_as_uint(Ps[(wrow + g + 8) * FSTR + kc * 8 + tg + 4]);
        }
#pragma unroll
        for (int nt = 0; nt < 8; nt++) {
#pragma unroll
            for (int kc = 0; kc < 8; kc++) {
                unsigned bb0 = __float_as_uint(Vs[(kc * 8 + tg) * FSTR + nt * 8 + g]);
                unsigned bb1 = __float_as_uint(Vs[(kc * 8 + tg + 4) * FSTR + nt * 8 + g]);
                mma8(of[nt], af[kc], bb0, bb1);
            }
        }
        __syncwarp();  // Ps reads done before next iteration overwrites
    }

    float inv_lo = 1.f / l_lo;
    float inv_hi = 1.f / l_hi;
    size_t row_lo = (base + qt * 64 + wrow + g) * D_MODEL + h * DK;
    size_t row_hi = row_lo + 8 * D_MODEL;
#pragma unroll
    for (int nt = 0; nt < 8; nt++) {
        int n0 = nt * 8 + 2 * tg;
        *(float2*)&ctx[row_lo + n0] = make_float2(of[nt][0] * inv_lo, of[nt][1] * inv_lo);
        *(float2*)&ctx[row_hi + n0] = make_float2(of[nt][2] * inv_hi, of[nt][3] * inv_hi);
    }
}

// ---------------------------------------------------------------------------
extern "C" void kernel_launch(void* const* d_in, const int* in_sizes, int n_in,
                              void* d_out, int out_size) {
    const float* x  = (const float*)d_in[0];
    const int*   am = (const int*)d_in[1];
    const float* wq = (const float*)d_in[2];
    const float* wk = (const float*)d_in[3];
    const float* wv = (const float*)d_in[4];
    const float* wo = (const float*)d_in[5];

    float *q, *k, *v, *ctx;
    cudaGetSymbolAddress((void**)&q,   g_q);
    cudaGetSymbolAddress((void**)&k,   g_k);
    cudaGetSymbolAddress((void**)&v,   g_v);
    cudaGetSymbolAddress((void**)&ctx, g_ctx);

    dim3 gg(D_MODEL / 128, MTOK / 128, 3);
    gemm_qkv<<<gg, 256>>>(x, wq, wk, wv, q, k, v);

    rope_kernel<<<(MTOK * (D_MODEL / 2)) / 256, 256>>>(q, k);

    cudaFuncSetAttribute(flash_mma,
                         cudaFuncAttributeMaxDynamicSharedMemorySize, FL_SMEM);
    flash_mma<<<dim3(SEQ / 64, HEADS, BATCH), 128, FL_SMEM>>>(q, k, v, am, ctx);

    dim3 go(D_MODEL / 128, MTOK / 128);
    gemm_out<<<go, 256>>>(ctx, wo, (float*)d_out);
}

// round 6
// speedup vs baseline: 8.8465x; 1.2191x over previous
#include <cuda_runtime.h>
#include <cstdint>

#define D_MODEL 1024
#define HEADS   16
#define DK      64
#define BATCH   2
#define SEQ     2048
#define MTOK    (BATCH * SEQ)   // 4096
#define NEGV    -1e9f

#define NW_ELEM (D_MODEL * D_MODEL)          // 1M floats per weight

// Scratch (allocation-free: static device globals)
__device__ float g_q[(size_t)MTOK * D_MODEL];
__device__ float g_k[(size_t)MTOK * D_MODEL];
__device__ float g_v[(size_t)MTOK * D_MODEL];
__device__ float g_ctx[(size_t)MTOK * D_MODEL];
__device__ float g_xr[(size_t)MTOK * D_MODEL];   // tf32-rounded x
__device__ float g_wr[(size_t)4 * NW_ELEM];      // tf32-rounded wq|wk|wv|wo

// ---------------------------------------------------------------------------
// tf32 helpers
// ---------------------------------------------------------------------------
__device__ __forceinline__ unsigned f2tf(float x) {
    unsigned r;
    asm("cvt.rna.tf32.f32 %0, %1;" : "=r"(r) : "f"(x));
    return r;
}
__device__ __forceinline__ float f2tf_f(float x) { return __uint_as_float(f2tf(x)); }

__device__ __forceinline__ void mma8(float* c, const unsigned* a, unsigned b0, unsigned b1) {
    asm volatile(
        "mma.sync.aligned.m16n8k8.row.col.f32.tf32.tf32.f32 "
        "{%0,%1,%2,%3},{%4,%5,%6,%7},{%8,%9},{%0,%1,%2,%3};"
        : "+f"(c[0]), "+f"(c[1]), "+f"(c[2]), "+f"(c[3])
        : "r"(a[0]), "r"(a[1]), "r"(a[2]), "r"(a[3]), "r"(b0), "r"(b1));
}

__device__ __forceinline__ void cp16(uint32_t dst, const float* src) {
    asm volatile("cp.async.cg.shared.global [%0], [%1], 16;" :: "r"(dst), "l"(src));
}
__device__ __forceinline__ void cp_commit() {
    asm volatile("cp.async.commit_group;");
}
template <int N> __device__ __forceinline__ void cp_wait() {
    asm volatile("cp.async.wait_group %0;" :: "n"(N));
}

// ---------------------------------------------------------------------------
// Pre-round x and the four weights to tf32 (rna). Makes GEMM loops cvt-free
// while keeping numerics bitwise-identical to converting inside the GEMM.
// ---------------------------------------------------------------------------
__global__ void round_all(const float* __restrict__ x,  const float* __restrict__ wq,
                          const float* __restrict__ wk, const float* __restrict__ wv,
                          const float* __restrict__ wo, float* __restrict__ xr,
                          float* __restrict__ wr) {
    const int NX = MTOK * D_MODEL / 4;   // float4 count for x
    const int NWq = NW_ELEM / 4;         // float4 count per weight (2^18)
    int i = blockIdx.x * blockDim.x + threadIdx.x;
    const float4* src;
    float4* dst;
    int off;
    if (i < NX) {
        src = (const float4*)x; dst = (float4*)xr; off = i;
    } else {
        int j = i - NX;
        int w = j >> 18;
        off = j & (NWq - 1);
        src = (const float4*)(w == 0 ? wq : w == 1 ? wk : w == 2 ? wv : wo);
        dst = (float4*)(wr + (size_t)w * NW_ELEM);
    }
    float4 t = src[off];
    dst[off] = make_float4(f2tf_f(t.x), f2tf_f(t.y), f2tf_f(t.z), f2tf_f(t.w));
}

// ---------------------------------------------------------------------------
// tf32 GEMM (NT): C[m][n] = sum_k A[m][k]*B[n][k]. Inputs pre-rounded to tf32.
// 128x128 tile, BK=32, cp.async double-buffered, 256 thr = 8 warps (2m x 4n).
// Smem row-major, word stride 36 -> all fragment loads conflict-free.
// ---------------------------------------------------------------------------
#define BK    32
#define GROW  36
#define STAGE (128 * GROW)                 // floats per stage per array
#define GEMM_SMEM (4 * STAGE * 4)          // 2 arrays x 2 stages = 73728 B

__device__ __forceinline__ void gemm_body(const float* __restrict__ A,
                                          const float* __restrict__ B,
                                          float* __restrict__ C) {
    extern __shared__ float sh[];
    float* As = sh;                // [2][STAGE]
    float* Bs = sh + 2 * STAGE;    // [2][STAGE]

    const int tid  = threadIdx.x;
    const int lane = tid & 31;
    const int wid  = tid >> 5;
    const int g    = lane >> 2;
    const int tg   = lane & 3;
    const int wm   = wid & 1;
    const int wn   = wid >> 1;
    const int bm   = blockIdx.y * 128;
    const int bn   = blockIdx.x * 128;

    // cp.async mapping: thread covers rows r0, r0+32, r0+64, r0+96 at 16B chunk kc
    const int r0 = tid >> 3;   // 0..31
    const int kc = tid & 7;    // 0..7
    const uint32_t sA = (uint32_t)__cvta_generic_to_shared(As) + (r0 * GROW + kc * 4) * 4;
    const uint32_t sB = (uint32_t)__cvta_generic_to_shared(Bs) + (r0 * GROW + kc * 4) * 4;
    const float* Ag = A + (size_t)(bm + r0) * D_MODEL + kc * 4;
    const float* Bg = B + (size_t)(bn + r0) * D_MODEL + kc * 4;

    float cf[4][4][4];
#pragma unroll
    for (int mt = 0; mt < 4; mt++)
#pragma unroll
        for (int nt = 0; nt < 4; nt++)
#pragma unroll
            for (int j = 0; j < 4; j++) cf[mt][nt][j] = 0.f;

    const int NIT = D_MODEL / BK;   // 32

    // prologue: stage 0
#pragma unroll
    for (int i = 0; i < 4; i++) {
        cp16(sA + i * 32 * GROW * 4, Ag + (size_t)i * 32 * D_MODEL);
        cp16(sB + i * 32 * GROW * 4, Bg + (size_t)i * 32 * D_MODEL);
    }
    cp_commit();

#pragma unroll 1
    for (int it = 0; it < NIT; it++) {
        if (it + 1 < NIT) {
            int s = (it + 1) & 1;
            int k0 = (it + 1) * BK;
            uint32_t dA = sA + s * STAGE * 4;
            uint32_t dB = sB + s * STAGE * 4;
#pragma unroll
            for (int i = 0; i < 4; i++) {
                cp16(dA + i * 32 * GROW * 4, Ag + k0 + (size_t)i * 32 * D_MODEL);
                cp16(dB + i * 32 * GROW * 4, Bg + k0 + (size_t)i * 32 * D_MODEL);
            }
            cp_commit();
            cp_wait<1>();
        } else {
            cp_wait<0>();
        }
        __syncthreads();

        const float* as = As + (it & 1) * STAGE;
        const float* bs = Bs + (it & 1) * STAGE;
#pragma unroll
        for (int kb = 0; kb < BK; kb += 8) {
            unsigned af[4][4];
#pragma unroll
            for (int mt = 0; mt < 4; mt++) {
                int m = wm * 64 + mt * 16 + g;
                af[mt][0] = __float_as_uint(as[m * GROW + kb + tg]);
                af[mt][1] = __float_as_uint(as[(m + 8) * GROW + kb + tg]);
                af[mt][2] = __float_as_uint(as[m * GROW + kb + tg + 4]);
                af[mt][3] = __float_as_uint(as[(m + 8) * GROW + kb + tg + 4]);
            }
#pragma unroll
            for (int nt = 0; nt < 4; nt++) {
                int n = wn * 32 + nt * 8 + g;
                unsigned bb0 = __float_as_uint(bs[n * GROW + kb + tg]);
                unsigned bb1 = __float_as_uint(bs[n * GROW + kb + tg + 4]);
#pragma unroll
                for (int mt = 0; mt < 4; mt++) mma8(cf[mt][nt], af[mt], bb0, bb1);
            }
        }
        __syncthreads();
    }

#pragma unroll
    for (int mt = 0; mt < 4; mt++) {
        int m0 = bm + wm * 64 + mt * 16 + g;
#pragma unroll
        for (int nt = 0; nt < 4; nt++) {
            int n0 = bn + wn * 32 + nt * 8 + 2 * tg;
            *(float2*)&C[(size_t)m0 * D_MODEL + n0] =
                make_float2(cf[mt][nt][0], cf[mt][nt][1]);
            *(float2*)&C[(size_t)(m0 + 8) * D_MODEL + n0] =
                make_float2(cf[mt][nt][2], cf[mt][nt][3]);
        }
    }
}

__global__ __launch_bounds__(256, 2) void gemm_out(const float* __restrict__ A,
                                                   const float* __restrict__ B,
                                                   float* __restrict__ C) {
    gemm_body(A, B, C);
}

__global__ __launch_bounds__(256, 2) void gemm_qkv(const float* __restrict__ x,
                                                   const float* __restrict__ w,
                                                   float* __restrict__ q,
                                                   float* __restrict__ k,
                                                   float* __restrict__ v) {
    const float* B = w + (size_t)blockIdx.z * NW_ELEM;
    float*       C = (blockIdx.z == 0) ? q : (blockIdx.z == 1) ? k : v;
    gemm_body(x, B, C);
}

// ---------------------------------------------------------------------------
// RoPE in-place on q and k.
// ---------------------------------------------------------------------------
__global__ void rope_kernel(float* __restrict__ q, float* __restrict__ k) {
    int idx = blockIdx.x * blockDim.x + threadIdx.x;
    if (idx >= MTOK * (D_MODEL / 2)) return;
    int col2 = idx & 511;
    int row  = idx >> 9;
    int d    = col2 & 31;
    int s    = row & (SEQ - 1);
    float inv = exp2f(-(float)d * (13.2877123795494935f / 32.0f));
    float ang = (float)s * inv;
    float sn, cs;
    sincosf(ang, &sn, &cs);
    size_t i = (size_t)row * D_MODEL + (size_t)col2 * 2;
    float2 qv = *(float2*)&q[i];
    float2 kv = *(float2*)&k[i];
    *(float2*)&q[i] = make_float2(qv.x * cs - qv.y * sn, qv.x * sn + qv.y * cs);
    *(float2*)&k[i] = make_float2(kv.x * cs - kv.y * sn, kv.x * sn + kv.y * cs);
}

// ---------------------------------------------------------------------------
// Flash attention, tf32 tensor cores. 64x64 tiles, 128 threads = 4 warps.
// Epilogue rounds ctx to tf32 so gemm_out needs no cvt.
// ---------------------------------------------------------------------------
#define FSTR 68
#define FL_SMEM (4 * 64 * FSTR * 4)   // 69632 B

__global__ __launch_bounds__(128) void flash_mma(const float* __restrict__ q,
                                                 const float* __restrict__ k,
                                                 const float* __restrict__ v,
                                                 const int* __restrict__ mask,
                                                 float* __restrict__ ctx) {
    extern __shared__ float sm[];
    float* Qs = sm;
    float* Ks = sm + 64 * FSTR;
    float* Vs = sm + 2 * 64 * FSTR;
    float* Ps = sm + 3 * 64 * FSTR;

    const int qt   = blockIdx.x;
    const int h    = blockIdx.y;
    const int b    = blockIdx.z;
    const int tid  = threadIdx.x;
    const int lane = tid & 31;
    const int wid  = tid >> 5;
    const int g    = lane >> 2;
    const int tg   = lane & 3;
    const int wrow = wid * 16;
    const size_t base = (size_t)b * SEQ;

#pragma unroll
    for (int it = 0; it < 8; it++) {
        int i    = it * 128 + tid;
        int row  = i >> 4;
        int col4 = (i & 15) * 4;
        float4 t = *(const float4*)&q[(base + qt * 64 + row) * D_MODEL + h * DK + col4];
        Qs[row * FSTR + col4 + 0] = f2tf_f(t.x * 0.125f);
        Qs[row * FSTR + col4 + 1] = f2tf_f(t.y * 0.125f);
        Qs[row * FSTR + col4 + 2] = f2tf_f(t.z * 0.125f);
        Qs[row * FSTR + col4 + 3] = f2tf_f(t.w * 0.125f);
    }

    float m_lo = -1e30f, m_hi = -1e30f, l_lo = 0.f, l_hi = 0.f;
    float of[8][4];
#pragma unroll
    for (int nt = 0; nt < 8; nt++)
#pragma unroll
        for (int j = 0; j < 4; j++) of[nt][j] = 0.f;

    for (int kt = 0; kt <= qt; kt++) {
        __syncthreads();
#pragma unroll
        for (int it = 0; it < 8; it++) {
            int i    = it * 128 + tid;
            int row  = i >> 4;
            int col4 = (i & 15) * 4;
            size_t gidx = (base + kt * 64 + row) * D_MODEL + h * DK + col4;
            float4 tk = *(const float4*)&k[gidx];
            float4 tv = *(const float4*)&v[gidx];
            Ks[row * FSTR + col4 + 0] = f2tf_f(tk.x);
            Ks[row * FSTR + col4 + 1] = f2tf_f(tk.y);
            Ks[row * FSTR + col4 + 2] = f2tf_f(tk.z);
            Ks[row * FSTR + col4 + 3] = f2tf_f(tk.w);
            Vs[row * FSTR + col4 + 0] = f2tf_f(tv.x);
            Vs[row * FSTR + col4 + 1] = f2tf_f(tv.y);
            Vs[row * FSTR + col4 + 2] = f2tf_f(tv.z);
            Vs[row * FSTR + col4 + 3] = f2tf_f(tv.w);
        }
        __syncthreads();

        unsigned af[8][4];
#pragma unroll
        for (int kc = 0; kc < 8; kc++) {
            af[kc][0] = __float_as_uint(Qs[(wrow + g) * FSTR + kc * 8 + tg]);
            af[kc][1] = __float_as_uint(Qs[(wrow + g + 8) * FSTR + kc * 8 + tg]);
            af[kc][2] = __float_as_uint(Qs[(wrow + g) * FSTR + kc * 8 + tg + 4]);
            af[kc][3] = __float_as_uint(Qs[(wrow + g + 8) * FSTR + kc * 8 + tg + 4]);
        }
        float sf[8][4];
#pragma unroll
        for (int nt = 0; nt < 8; nt++) {
#pragma unroll
            for (int j = 0; j < 4; j++) sf[nt][j] = 0.f;
#pragma unroll
            for (int kc = 0; kc < 8; kc++) {
                unsigned bb0 = __float_as_uint(Ks[(nt * 8 + g) * FSTR + kc * 8 + tg]);
                unsigned bb1 = __float_as_uint(Ks[(nt * 8 + g) * FSTR + kc * 8 + tg + 4]);
                mma8(sf[nt], af[kc], bb0, bb1);
            }
        }

#pragma unroll
        for (int nt = 0; nt < 8; nt++) {
            int colg = kt * 64 + nt * 8 + 2 * tg;
            if (mask[base + colg] == 0)     { sf[nt][0] = NEGV; sf[nt][2] = NEGV; }
            if (mask[base + colg + 1] == 0) { sf[nt][1] = NEGV; sf[nt][3] = NEGV; }
        }
        if (kt == qt) {
#pragma unroll
            for (int nt = 0; nt < 8; nt++) {
                int c    = nt * 8 + 2 * tg;
                int r_lo = wrow + g;
                int r_hi = r_lo + 8;
                if (c > r_lo)     sf[nt][0] = NEGV;
                if (c + 1 > r_lo) sf[nt][1] = NEGV;
                if (c > r_hi)     sf[nt][2] = NEGV;
                if (c + 1 > r_hi) sf[nt][3] = NEGV;
            }
        }

        float mt_lo = sf[0][0], mt_hi = sf[0][2];
#pragma unroll
        for (int nt = 0; nt < 8; nt++) {
            mt_lo = fmaxf(mt_lo, fmaxf(sf[nt][0], sf[nt][1]));
            mt_hi = fmaxf(mt_hi, fmaxf(sf[nt][2], sf[nt][3]));
        }
        mt_lo = fmaxf(mt_lo, __shfl_xor_sync(0xffffffffu, mt_lo, 1));
        mt_lo = fmaxf(mt_lo, __shfl_xor_sync(0xffffffffu, mt_lo, 2));
        mt_hi = fmaxf(mt_hi, __shfl_xor_sync(0xffffffffu, mt_hi, 1));
        mt_hi = fmaxf(mt_hi, __shfl_xor_sync(0xffffffffu, mt_hi, 2));
        float mn_lo = fmaxf(m_lo, mt_lo);
        float mn_hi = fmaxf(m_hi, mt_hi);

        float lt_lo = 0.f, lt_hi = 0.f;
#pragma unroll
        for (int nt = 0; nt < 8; nt++) {
            sf[nt][0] = __expf(sf[nt][0] - mn_lo);
            sf[nt][1] = __expf(sf[nt][1] - mn_lo);
            sf[nt][2] = __expf(sf[nt][2] - mn_hi);
            sf[nt][3] = __expf(sf[nt][3] - mn_hi);
            lt_lo += sf[nt][0] + sf[nt][1];
            lt_hi += sf[nt][2] + sf[nt][3];
        }
        lt_lo += __shfl_xor_sync(0xffffffffu, lt_lo, 1);
        lt_lo += __shfl_xor_sync(0xffffffffu, lt_lo, 2);
        lt_hi += __shfl_xor_sync(0xffffffffu, lt_hi, 1);
        lt_hi += __shfl_xor_sync(0xffffffffu, lt_hi, 2);

        float a_lo = __expf(m_lo - mn_lo);
        float a_hi = __expf(m_hi - mn_hi);
        l_lo = l_lo * a_lo + lt_lo;
        l_hi = l_hi * a_hi + lt_hi;
        m_lo = mn_lo;
        m_hi = mn_hi;
#pragma unroll
        for (int nt = 0; nt < 8; nt++) {
            of[nt][0] *= a_lo;
            of[nt][1] *= a_lo;
            of[nt][2] *= a_hi;
            of[nt][3] *= a_hi;
        }

#pragma unroll
        for (int nt = 0; nt < 8; nt++) {
            int pidx = (wrow + g) * FSTR + nt * 8 + 2 * tg;
            *(float2*)&Ps[pidx] = make_float2(f2tf_f(sf[nt][0]), f2tf_f(sf[nt][1]));
            *(float2*)&Ps[pidx + 8 * FSTR] = make_float2(f2tf_f(sf[nt][2]), f2tf_f(sf[nt][3]));
        }
        __syncwarp();

#pragma unroll
        for (int kc = 0; kc < 8; kc++) {
            af[kc][0] = __float_as_uint(Ps[(wrow + g) * FSTR + kc * 8 + tg]);
            af[kc][1] = __float_as_uint(Ps[(wrow + g + 8) * FSTR + kc * 8 + tg]);
            af[kc][2] = __float_as_uint(Ps[(wrow + g) * FSTR + kc * 8 + tg + 4]);
            af[kc][3] = __float_as_uint(Ps[(wrow + g + 8) * FSTR + kc * 8 + tg + 4]);
        }
#pragma unroll
        for (int nt = 0; nt < 8; nt++) {
#pragma unroll
            for (int kc = 0; kc < 8; kc++) {
                unsigned bb0 = __float_as_uint(Vs[(kc * 8 + tg) * FSTR + nt * 8 + g]);
                unsigned bb1 = __float_as_uint(Vs[(kc * 8 + tg + 4) * FSTR + nt * 8 + g]);
                mma8(of[nt], af[kc], bb0, bb1);
            }
        }
        __syncwarp();
    }

    float inv_lo = 1.f / l_lo;
    float inv_hi = 1.f / l_hi;
    size_t row_lo = (base + qt * 64 + wrow + g) * D_MODEL + h * DK;
    size_t row_hi = row_lo + 8 * D_MODEL;
#pragma unroll
    for (int nt = 0; nt < 8; nt++) {
        int n0 = nt * 8 + 2 * tg;
        *(float2*)&ctx[row_lo + n0] =
            make_float2(f2tf_f(of[nt][0] * inv_lo), f2tf_f(of[nt][1] * inv_lo));
        *(float2*)&ctx[row_hi + n0] =
            make_float2(f2tf_f(of[nt][2] * inv_hi), f2tf_f(of[nt][3] * inv_hi));
    }
}

// ---------------------------------------------------------------------------
extern "C" void kernel_launch(void* const* d_in, const int* in_sizes, int n_in,
                              void* d_out, int out_size) {
    const float* x  = (const float*)d_in[0];
    const int*   am = (const int*)d_in[1];
    const float* wq = (const float*)d_in[2];
    const float* wk = (const float*)d_in[3];
    const float* wv = (const float*)d_in[4];
    const float* wo = (const float*)d_in[5];

    float *q, *k, *v, *ctx, *xr, *wr;
    cudaGetSymbolAddress((void**)&q,   g_q);
    cudaGetSymbolAddress((void**)&k,   g_k);
    cudaGetSymbolAddress((void**)&v,   g_v);
    cudaGetSymbolAddress((void**)&ctx, g_ctx);
    cudaGetSymbolAddress((void**)&xr,  g_xr);
    cudaGetSymbolAddress((void**)&wr,  g_wr);

    cudaFuncSetAttribute(gemm_qkv, cudaFuncAttributeMaxDynamicSharedMemorySize, GEMM_SMEM);
    cudaFuncSetAttribute(gemm_out, cudaFuncAttributeMaxDynamicSharedMemorySize, GEMM_SMEM);
    cudaFuncSetAttribute(flash_mma, cudaFuncAttributeMaxDynamicSharedMemorySize, FL_SMEM);

    // total float4 work items: x (1M) + 4 weights (4 * 256K) = 2M -> 8192 blocks
    round_all<<<8192, 256>>>(x, wq, wk, wv, wo, xr, wr);

    dim3 gg(D_MODEL / 128, MTOK / 128, 3);
    gemm_qkv<<<gg, 256, GEMM_SMEM>>>(xr, wr, q, k, v);

    rope_kernel<<<(MTOK * (D_MODEL / 2)) / 256, 256>>>(q, k);

    flash_mma<<<dim3(SEQ / 64, HEADS, BATCH), 128, FL_SMEM>>>(q, k, v, am, ctx);

    dim3 go(D_MODEL / 128, MTOK / 128);
    gemm_out<<<go, 256, GEMM_SMEM>>>(ctx, wr + (size_t)3 * NW_ELEM, (float*)d_out);
}

// round 7
// speedup vs baseline: 9.6493x; 1.0908x over previous
#include <cuda_runtime.h>
#include <cstdint>

#define D_MODEL 1024
#define HEADS   16
#define DK      64
#define BATCH   2
#define SEQ     2048
#define MTOK    (BATCH * SEQ)   // 4096
#define NEGV    -1e9f

#define NW_ELEM (D_MODEL * D_MODEL)

// Scratch (allocation-free: static device globals)
__device__ float g_q[(size_t)MTOK * D_MODEL];
__device__ float g_k[(size_t)MTOK * D_MODEL];
__device__ float g_v[(size_t)MTOK * D_MODEL];
__device__ float g_ctx[(size_t)MTOK * D_MODEL];
__device__ float g_xr[(size_t)MTOK * D_MODEL];   // tf32-rounded x
__device__ float g_wr[(size_t)4 * NW_ELEM];      // tf32-rounded wq|wk|wv|wo

// ---------------------------------------------------------------------------
__device__ __forceinline__ unsigned f2tf(float x) {
    unsigned r;
    asm("cvt.rna.tf32.f32 %0, %1;" : "=r"(r) : "f"(x));
    return r;
}
__device__ __forceinline__ float f2tf_f(float x) { return __uint_as_float(f2tf(x)); }

__device__ __forceinline__ void mma8(float* c, const unsigned* a, unsigned b0, unsigned b1) {
    asm volatile(
        "mma.sync.aligned.m16n8k8.row.col.f32.tf32.tf32.f32 "
        "{%0,%1,%2,%3},{%4,%5,%6,%7},{%8,%9},{%0,%1,%2,%3};"
        : "+f"(c[0]), "+f"(c[1]), "+f"(c[2]), "+f"(c[3])
        : "r"(a[0]), "r"(a[1]), "r"(a[2]), "r"(a[3]), "r"(b0), "r"(b1));
}

__device__ __forceinline__ void cp16(uint32_t dst, const float* src) {
    asm volatile("cp.async.cg.shared.global [%0], [%1], 16;" :: "r"(dst), "l"(src));
}
__device__ __forceinline__ void cp_commit() {
    asm volatile("cp.async.commit_group;");
}
template <int N> __device__ __forceinline__ void cp_wait() {
    asm volatile("cp.async.wait_group %0;" :: "n"(N));
}

// ---------------------------------------------------------------------------
// Pre-round x and the four weights to tf32 (rna).
// ---------------------------------------------------------------------------
__global__ void round_all(const float* __restrict__ x,  const float* __restrict__ wq,
                          const float* __restrict__ wk, const float* __restrict__ wv,
                          const float* __restrict__ wo, float* __restrict__ xr,
                          float* __restrict__ wr) {
    const int NX = MTOK * D_MODEL / 4;
    const int NWq = NW_ELEM / 4;
    int i = blockIdx.x * blockDim.x + threadIdx.x;
    const float4* src;
    float4* dst;
    int off;
    if (i < NX) {
        src = (const float4*)x; dst = (float4*)xr; off = i;
    } else {
        int j = i - NX;
        int w = j >> 18;
        off = j & (NWq - 1);
        src = (const float4*)(w == 0 ? wq : w == 1 ? wk : w == 2 ? wv : wo);
        dst = (float4*)(wr + (size_t)w * NW_ELEM);
    }
    float4 t = src[off];
    dst[off] = make_float4(f2tf_f(t.x), f2tf_f(t.y), f2tf_f(t.z), f2tf_f(t.w));
}

// ---------------------------------------------------------------------------
// tf32 GEMM (NT), 128x128 tile, BK=32, cp.async double-buffered. (unchanged)
// ---------------------------------------------------------------------------
#define BK    32
#define GROW  36
#define STAGE (128 * GROW)
#define GEMM_SMEM (4 * STAGE * 4)

__device__ __forceinline__ void gemm_body(const float* __restrict__ A,
                                          const float* __restrict__ B,
                                          float* __restrict__ C) {
    extern __shared__ float sh[];
    float* As = sh;
    float* Bs = sh + 2 * STAGE;

    const int tid  = threadIdx.x;
    const int lane = tid & 31;
    const int wid  = tid >> 5;
    const int g    = lane >> 2;
    const int tg   = lane & 3;
    const int wm   = wid & 1;
    const int wn   = wid >> 1;
    const int bm   = blockIdx.y * 128;
    const int bn   = blockIdx.x * 128;

    const int r0 = tid >> 3;
    const int kc = tid & 7;
    const uint32_t sA = (uint32_t)__cvta_generic_to_shared(As) + (r0 * GROW + kc * 4) * 4;
    const uint32_t sB = (uint32_t)__cvta_generic_to_shared(Bs) + (r0 * GROW + kc * 4) * 4;
    const float* Ag = A + (size_t)(bm + r0) * D_MODEL + kc * 4;
    const float* Bg = B + (size_t)(bn + r0) * D_MODEL + kc * 4;

    float cf[4][4][4];
#pragma unroll
    for (int mt = 0; mt < 4; mt++)
#pragma unroll
        for (int nt = 0; nt < 4; nt++)
#pragma unroll
            for (int j = 0; j < 4; j++) cf[mt][nt][j] = 0.f;

    const int NIT = D_MODEL / BK;

#pragma unroll
    for (int i = 0; i < 4; i++) {
        cp16(sA + i * 32 * GROW * 4, Ag + (size_t)i * 32 * D_MODEL);
        cp16(sB + i * 32 * GROW * 4, Bg + (size_t)i * 32 * D_MODEL);
    }
    cp_commit();

#pragma unroll 1
    for (int it = 0; it < NIT; it++) {
        if (it + 1 < NIT) {
            int s = (it + 1) & 1;
            int k0 = (it + 1) * BK;
            uint32_t dA = sA + s * STAGE * 4;
            uint32_t dB = sB + s * STAGE * 4;
#pragma unroll
            for (int i = 0; i < 4; i++) {
                cp16(dA + i * 32 * GROW * 4, Ag + k0 + (size_t)i * 32 * D_MODEL);
                cp16(dB + i * 32 * GROW * 4, Bg + k0 + (size_t)i * 32 * D_MODEL);
            }
            cp_commit();
            cp_wait<1>();
        } else {
            cp_wait<0>();
        }
        __syncthreads();

        const float* as = As + (it & 1) * STAGE;
        const float* bs = Bs + (it & 1) * STAGE;
#pragma unroll
        for (int kb = 0; kb < BK; kb += 8) {
            unsigned af[4][4];
#pragma unroll
            for (int mt = 0; mt < 4; mt++) {
                int m = wm * 64 + mt * 16 + g;
                af[mt][0] = __float_as_uint(as[m * GROW + kb + tg]);
                af[mt][1] = __float_as_uint(as[(m + 8) * GROW + kb + tg]);
                af[mt][2] = __float_as_uint(as[m * GROW + kb + tg + 4]);
                af[mt][3] = __float_as_uint(as[(m + 8) * GROW + kb + tg + 4]);
            }
#pragma unroll
            for (int nt = 0; nt < 4; nt++) {
                int n = wn * 32 + nt * 8 + g;
                unsigned bb0 = __float_as_uint(bs[n * GROW + kb + tg]);
                unsigned bb1 = __float_as_uint(bs[n * GROW + kb + tg + 4]);
#pragma unroll
                for (int mt = 0; mt < 4; mt++) mma8(cf[mt][nt], af[mt], bb0, bb1);
            }
        }
        __syncthreads();
    }

#pragma unroll
    for (int mt = 0; mt < 4; mt++) {
        int m0 = bm + wm * 64 + mt * 16 + g;
#pragma unroll
        for (int nt = 0; nt < 4; nt++) {
            int n0 = bn + wn * 32 + nt * 8 + 2 * tg;
            *(float2*)&C[(size_t)m0 * D_MODEL + n0] =
                make_float2(cf[mt][nt][0], cf[mt][nt][1]);
            *(float2*)&C[(size_t)(m0 + 8) * D_MODEL + n0] =
                make_float2(cf[mt][nt][2], cf[mt][nt][3]);
        }
    }
}

__global__ __launch_bounds__(256, 2) void gemm_out(const float* __restrict__ A,
                                                   const float* __restrict__ B,
                                                   float* __restrict__ C) {
    gemm_body(A, B, C);
}

__global__ __launch_bounds__(256, 2) void gemm_qkv(const float* __restrict__ x,
                                                   const float* __restrict__ w,
                                                   float* __restrict__ q,
                                                   float* __restrict__ k,
                                                   float* __restrict__ v) {
    const float* B = w + (size_t)blockIdx.z * NW_ELEM;
    float*       C = (blockIdx.z == 0) ? q : (blockIdx.z == 1) ? k : v;
    gemm_body(x, B, C);
}

// ---------------------------------------------------------------------------
// RoPE in-place on q and k; also pre-scales q by 1/8 and rounds q,k,v to tf32
// so the flash kernel can cp.async raw bits (bit-identical to rounding there).
// ---------------------------------------------------------------------------
__global__ void rope_kernel(float* __restrict__ q, float* __restrict__ k,
                            float* __restrict__ v) {
    int idx = blockIdx.x * blockDim.x + threadIdx.x;
    if (idx >= MTOK * (D_MODEL / 2)) return;
    int col2 = idx & 511;
    int row  = idx >> 9;
    int d    = col2 & 31;
    int s    = row & (SEQ - 1);
    float inv = exp2f(-(float)d * (13.2877123795494935f / 32.0f));
    float ang = (float)s * inv;
    float sn, cs;
    sincosf(ang, &sn, &cs);
    size_t i = (size_t)row * D_MODEL + (size_t)col2 * 2;
    float2 qv = *(float2*)&q[i];
    float2 kv = *(float2*)&k[i];
    float2 vv = *(float2*)&v[i];
    *(float2*)&q[i] = make_float2(f2tf_f((qv.x * cs - qv.y * sn) * 0.125f),
                                  f2tf_f((qv.x * sn + qv.y * cs) * 0.125f));
    *(float2*)&k[i] = make_float2(f2tf_f(kv.x * cs - kv.y * sn),
                                  f2tf_f(kv.x * sn + kv.y * cs));
    *(float2*)&v[i] = make_float2(f2tf_f(vv.x), f2tf_f(vv.y));
}

// ---------------------------------------------------------------------------
// Flash attention v2: 128x64 tiles, 256 threads = 8 warps (16 q rows each).
// cp.async loads (inputs pre-rounded tf32). Q fragments hoisted to registers.
// Pitches: Qs/Ks/Ps = 68 (row-pattern conflict-free), Vs = 72 (col-pattern
// conflict-free: bank = 8*tg + g). Mask staged in smem.
// ---------------------------------------------------------------------------
#define FQ 68
#define FV 72
#define OQ 0
#define OKs 8704            // 128*68
#define OVs 13056           // OKs + 64*68
#define OP  17664           // OVs + 64*72
#define OM  26368           // OP + 128*68
#define FL2_SMEM ((OM + 64) * 4)   // 105728 B

__global__ __launch_bounds__(256, 2) void flash2(const float* __restrict__ q,
                                                 const float* __restrict__ k,
                                                 const float* __restrict__ v,
                                                 const int* __restrict__ mask,
                                                 float* __restrict__ ctx) {
    extern __shared__ float sm[];
    float* Qs = sm + OQ;
    float* Ks = sm + OKs;
    float* Vs = sm + OVs;
    float* Ps = sm + OP;
    int*   Ms = (int*)(sm + OM);

    const int T    = gridDim.x - 1 - blockIdx.x;   // heavy tiles first
    const int h    = blockIdx.y;
    const int b    = blockIdx.z;
    const int tid  = threadIdx.x;
    const int lane = tid & 31;
    const int wid  = tid >> 5;
    const int g    = lane >> 2;
    const int tg   = lane & 3;
    const int wrow = wid * 16;
    const size_t base = (size_t)b * SEQ;
    const uint32_t smb = (uint32_t)__cvta_generic_to_shared(sm);

    // Q tile: 128 rows x 64 cols = 2048 16B chunks, 8 per thread.
#pragma unroll
    for (int i = 0; i < 8; i++) {
        int c = i * 256 + tid;
        int row = c >> 4, col4 = (c & 15) * 4;
        cp16(smb + (OQ + row * FQ + col4) * 4,
             &q[(base + T * 128 + row) * D_MODEL + h * DK + col4]);
    }

    float m_lo = -1e30f, m_hi = -1e30f, l_lo = 0.f, l_hi = 0.f;
    float of[8][4];
#pragma unroll
    for (int nt = 0; nt < 8; nt++)
#pragma unroll
        for (int j = 0; j < 4; j++) of[nt][j] = 0.f;

    unsigned qf[8][4];
    const int nkt = 2 * T + 2;

#pragma unroll 1
    for (int kt = 0; kt < nkt; kt++) {
        __syncthreads();   // prior tile's Ks/Vs/Ms reads done
        // K/V tile: 64 x 64 = 1024 chunks each, 4 per thread.
#pragma unroll
        for (int i = 0; i < 4; i++) {
            int c = i * 256 + tid;
            int row = c >> 4, col4 = (c & 15) * 4;
            size_t gidx = (base + kt * 64 + row) * D_MODEL + h * DK + col4;
            cp16(smb + (OKs + row * FQ + col4) * 4, &k[gidx]);
            cp16(smb + (OVs + row * FV + col4) * 4, &v[gidx]);
        }
        if (tid < 64) Ms[tid] = mask[base + kt * 64 + tid];
        cp_commit();
        cp_wait<0>();
        __syncthreads();

        if (kt == 0) {   // Q now resident: hoist fragments (kt-invariant)
#pragma unroll
            for (int kc = 0; kc < 8; kc++) {
                qf[kc][0] = __float_as_uint(Qs[(wrow + g) * FQ + kc * 8 + tg]);
                qf[kc][1] = __float_as_uint(Qs[(wrow + g + 8) * FQ + kc * 8 + tg]);
                qf[kc][2] = __float_as_uint(Qs[(wrow + g) * FQ + kc * 8 + tg + 4]);
                qf[kc][3] = __float_as_uint(Qs[(wrow + g + 8) * FQ + kc * 8 + tg + 4]);
            }
        }

        // ---- S = Q . K^T ----
        float sf[8][4];
#pragma unroll
        for (int nt = 0; nt < 8; nt++) {
#pragma unroll
            for (int j = 0; j < 4; j++) sf[nt][j] = 0.f;
#pragma unroll
            for (int kc = 0; kc < 8; kc++) {
                unsigned bb0 = __float_as_uint(Ks[(nt * 8 + g) * FQ + kc * 8 + tg]);
                unsigned bb1 = __float_as_uint(Ks[(nt * 8 + g) * FQ + kc * 8 + tg + 4]);
                mma8(sf[nt], qf[kc], bb0, bb1);
            }
        }

        // ---- padding mask (from smem) ----
#pragma unroll
        for (int nt = 0; nt < 8; nt++) {
            if (Ms[nt * 8 + 2 * tg] == 0)     { sf[nt][0] = NEGV; sf[nt][2] = NEGV; }
            if (Ms[nt * 8 + 2 * tg + 1] == 0) { sf[nt][1] = NEGV; sf[nt][3] = NEGV; }
        }
        // ---- causal mask (only tiles at/after this warp's diagonal) ----
        if (kt * 64 + 63 > T * 128 + wrow) {
            int r_lo = T * 128 + wrow + g;
            int r_hi = r_lo + 8;
#pragma unroll
            for (int nt = 0; nt < 8; nt++) {
                int c = kt * 64 + nt * 8 + 2 * tg;
                if (c > r_lo)     sf[nt][0] = NEGV;
                if (c + 1 > r_lo) sf[nt][1] = NEGV;
                if (c > r_hi)     sf[nt][2] = NEGV;
                if (c + 1 > r_hi) sf[nt][3] = NEGV;
            }
        }

        // ---- online softmax ----
        float mt_lo = sf[0][0], mt_hi = sf[0][2];
#pragma unroll
        for (int nt = 0; nt < 8; nt++) {
            mt_lo = fmaxf(mt_lo, fmaxf(sf[nt][0], sf[nt][1]));
            mt_hi = fmaxf(mt_hi, fmaxf(sf[nt][2], sf[nt][3]));
        }
        mt_lo = fmaxf(mt_lo, __shfl_xor_sync(0xffffffffu, mt_lo, 1));
        mt_lo = fmaxf(mt_lo, __shfl_xor_sync(0xffffffffu, mt_lo, 2));
        mt_hi = fmaxf(mt_hi, __shfl_xor_sync(0xffffffffu, mt_hi, 1));
        mt_hi = fmaxf(mt_hi, __shfl_xor_sync(0xffffffffu, mt_hi, 2));
        float mn_lo = fmaxf(m_lo, mt_lo);
        float mn_hi = fmaxf(m_hi, mt_hi);

        float lt_lo = 0.f, lt_hi = 0.f;
#pragma unroll
        for (int nt = 0; nt < 8; nt++) {
            sf[nt][0] = __expf(sf[nt][0] - mn_lo);
            sf[nt][1] = __expf(sf[nt][1] - mn_lo);
            sf[nt][2] = __expf(sf[nt][2] - mn_hi);
            sf[nt][3] = __expf(sf[nt][3] - mn_hi);
            lt_lo += sf[nt][0] + sf[nt][1];
            lt_hi += sf[nt][2] + sf[nt][3];
        }
        lt_lo += __shfl_xor_sync(0xffffffffu, lt_lo, 1);
        lt_lo += __shfl_xor_sync(0xffffffffu, lt_lo, 2);
        lt_hi += __shfl_xor_sync(0xffffffffu, lt_hi, 1);
        lt_hi += __shfl_xor_sync(0xffffffffu, lt_hi, 2);

        float a_lo = __expf(m_lo - mn_lo);
        float a_hi = __expf(m_hi - mn_hi);
        l_lo = l_lo * a_lo + lt_lo;
        l_hi = l_hi * a_hi + lt_hi;
        m_lo = mn_lo;
        m_hi = mn_hi;
#pragma unroll
        for (int nt = 0; nt < 8; nt++) {
            of[nt][0] *= a_lo;
            of[nt][1] *= a_lo;
            of[nt][2] *= a_hi;
            of[nt][3] *= a_hi;
        }

        // ---- P -> per-warp smem slab ----
#pragma unroll
        for (int nt = 0; nt < 8; nt++) {
            int pidx = (wrow + g) * FQ + nt * 8 + 2 * tg;
            *(float2*)&Ps[pidx] = make_float2(f2tf_f(sf[nt][0]), f2tf_f(sf[nt][1]));
            *(float2*)&Ps[pidx + 8 * FQ] = make_float2(f2tf_f(sf[nt][2]), f2tf_f(sf[nt][3]));
        }
        __syncwarp();

        // ---- O += P . V ----
        unsigned af[8][4];
#pragma unroll
        for (int kc = 0; kc < 8; kc++) {
            af[kc][0] = __float_as_uint(Ps[(wrow + g) * FQ + kc * 8 + tg]);
            af[kc][1] = __float_as_uint(Ps[(wrow + g + 8) * FQ + kc * 8 + tg]);
            af[kc][2] = __float_as_uint(Ps[(wrow + g) * FQ + kc * 8 + tg + 4]);
            af[kc][3] = __float_as_uint(Ps[(wrow + g + 8) * FQ + kc * 8 + tg + 4]);
        }
#pragma unroll
        for (int nt = 0; nt < 8; nt++) {
#pragma unroll
            for (int kc = 0; kc < 8; kc++) {
                unsigned bb0 = __float_as_uint(Vs[(kc * 8 + tg) * FV + nt * 8 + g]);
                unsigned bb1 = __float_as_uint(Vs[(kc * 8 + tg + 4) * FV + nt * 8 + g]);
                mma8(of[nt], af[kc], bb0, bb1);
            }
        }
        __syncwarp();   // Ps reads done before next tile overwrites
    }

    float inv_lo = 1.f / l_lo;
    float inv_hi = 1.f / l_hi;
    size_t row_lo = (base + T * 128 + wrow + g) * D_MODEL + h * DK;
    size_t row_hi = row_lo + 8 * D_MODEL;
#pragma unroll
    for (int nt = 0; nt < 8; nt++) {
        int n0 = nt * 8 + 2 * tg;
        *(float2*)&ctx[row_lo + n0] =
            make_float2(f2tf_f(of[nt][0] * inv_lo), f2tf_f(of[nt][1] * inv_lo));
        *(float2*)&ctx[row_hi + n0] =
            make_float2(f2tf_f(of[nt][2] * inv_hi), f2tf_f(of[nt][3] * inv_hi));
    }
}

// ---------------------------------------------------------------------------
extern "C" void kernel_launch(void* const* d_in, const int* in_sizes, int n_in,
                              void* d_out, int out_size) {
    const float* x  = (const float*)d_in[0];
    const int*   am = (const int*)d_in[1];
    const float* wq = (const float*)d_in[2];
    const float* wk = (const float*)d_in[3];
    const float* wv = (const float*)d_in[4];
    const float* wo = (const float*)d_in[5];

    float *q, *k, *v, *ctx, *xr, *wr;
    cudaGetSymbolAddress((void**)&q,   g_q);
    cudaGetSymbolAddress((void**)&k,   g_k);
    cudaGetSymbolAddress((void**)&v,   g_v);
    cudaGetSymbolAddress((void**)&ctx, g_ctx);
    cudaGetSymbolAddress((void**)&xr,  g_xr);
    cudaGetSymbolAddress((void**)&wr,  g_wr);

    cudaFuncSetAttribute(gemm_qkv, cudaFuncAttributeMaxDynamicSharedMemorySize, GEMM_SMEM);
    cudaFuncSetAttribute(gemm_out, cudaFuncAttributeMaxDynamicSharedMemorySize, GEMM_SMEM);
    cudaFuncSetAttribute(flash2,   cudaFuncAttributeMaxDynamicSharedMemorySize, FL2_SMEM);

    round_all<<<8192, 256>>>(x, wq, wk, wv, wo, xr, wr);

    dim3 gg(D_MODEL / 128, MTOK / 128, 3);
    gemm_qkv<<<gg, 256, GEMM_SMEM>>>(xr, wr, q, k, v);

    rope_kernel<<<(MTOK * (D_MODEL / 2)) / 256, 256>>>(q, k, v);

    flash2<<<dim3(SEQ / 128, HEADS, BATCH), 256, FL2_SMEM>>>(q, k, v, am, ctx);

    dim3 go(D_MODEL / 128, MTOK / 128);
    gemm_out<<<go, 256, GEMM_SMEM>>>(ctx, wr + (size_t)3 * NW_ELEM, (float*)d_out);
}